// round 1
// baseline (speedup 1.0000x reference)
#include <cuda_runtime.h>

// Swin WindowAttention fused kernel (fp32 baseline).
// B=4096 windows, N=49 tokens, C=128, 4 heads x 32, nW=64 masks.

#define NTOK   49
#define DIMC   128
#define NH     4
#define HD     32
#define NWIN   64
#define QKSCALE 0.17677669529663687f   // 32^-0.5

#define RPAD   56        // padded token rows (multiple of 8)
#define WTS    132       // staged transposed-weight row stride (floats)
#define AST    52        // attn row stride (floats)

// shared memory layout (floats)
#define OFF_X    0                         // 7168  : x tile -> later kT -> later O
#define OFF_W    (RPAD*DIMC)               // 16896 : staged W^T chunk -> later attn P
#define OFF_QKV  (OFF_X + RPAD*DIMC + DIMC*WTS)   // 18816 : qkv -> later proj W^T
#define SMEM_FLOATS (OFF_QKV + NTOK*384)   // 42880 floats = 171,520 B

// Precombined (bias + mask) per (window-in-image, head): 64*4*49*49 floats = 2.46 MB
__device__ float g_cmb[NWIN * NH * NTOK * NTOK];

__global__ void prep_bias_kernel(const float* __restrict__ mask,
                                 const float* __restrict__ bias_table,
                                 const int*   __restrict__ rel_index) {
    int idx = blockIdx.x * 256 + threadIdx.x;
    if (idx >= NWIN * NH * NTOK * NTOK) return;
    int w  = idx / (NH * NTOK * NTOK);
    int r  = idx % (NH * NTOK * NTOK);
    int h  = r / (NTOK * NTOK);
    int ij = r % (NTOK * NTOK);
    g_cmb[idx] = bias_table[rel_index[ij] * NH + h] + mask[w * NTOK * NTOK + ij];
}

__global__ __launch_bounds__(256, 1)
void win_attn_kernel(const float* __restrict__ x,
                     const float* __restrict__ qkv_w,
                     const float* __restrict__ qkv_b,
                     const float* __restrict__ proj_w,
                     const float* __restrict__ proj_b,
                     float* __restrict__ out) {
    extern __shared__ float sm[];
    float* sx   = sm + OFF_X;     // x tile (RPAD x 128)
    float* sw   = sm + OFF_W;     // W^T chunk (128 x WTS)
    float* sqkv = sm + OFF_QKV;   // qkv (49 x 384)

    const int tid = threadIdx.x;
    const int tx  = tid & 31;
    const int ty  = tid >> 5;     // 0..7
    const int b   = blockIdx.x;

    // ---------- load x (zero-padded to RPAD rows) ----------
    {
        const float4* xg  = (const float4*)(x + (size_t)b * NTOK * DIMC);
        float4*       sx4 = (float4*)sx;
        #pragma unroll
        for (int it = 0; it < (RPAD * DIMC / 4) / 256; it++) {
            int i = tid + it * 256;                  // 0..1791
            float4 v = make_float4(0.f, 0.f, 0.f, 0.f);
            if (i < (NTOK * DIMC) / 4) v = xg[i];
            sx4[i] = v;
        }
    }

    // ---------- qkv = x @ W^T + b  (3 chunks of 128 cols) ----------
    for (int ch = 0; ch < 3; ch++) {
        if (ch) __syncthreads();   // protect sw reuse
        // stage W chunk transposed: sw[k][c]
        {
            const float4* wg = (const float4*)(qkv_w + (size_t)ch * 128 * DIMC);
            #pragma unroll
            for (int it = 0; it < 16; it++) {
                int idx = tid + it * 256;     // 0..4095
                int c   = idx >> 5;           // row within chunk
                int kq  = idx & 31;           // float4 index along k
                float4 v = wg[c * 32 + kq];
                sw[(4 * kq + 0) * WTS + c] = v.x;
                sw[(4 * kq + 1) * WTS + c] = v.y;
                sw[(4 * kq + 2) * WTS + c] = v.z;
                sw[(4 * kq + 3) * WTS + c] = v.w;
            }
        }
        __syncthreads();

        float acc[7][4];
        #pragma unroll
        for (int t = 0; t < 7; t++)
            #pragma unroll
            for (int u = 0; u < 4; u++) acc[t][u] = 0.f;

        #pragma unroll 4
        for (int k = 0; k < DIMC; k++) {
            float wv[4];
            #pragma unroll
            for (int u = 0; u < 4; u++) wv[u] = sw[k * WTS + tx + 32 * u];
            #pragma unroll
            for (int t = 0; t < 7; t++) {
                float xv = sx[(ty + 8 * t) * DIMC + k];   // broadcast
                #pragma unroll
                for (int u = 0; u < 4; u++) acc[t][u] = fmaf(xv, wv[u], acc[t][u]);
            }
        }

        float scl = (ch == 0) ? QKSCALE : 1.f;   // fold attn scale into q
        #pragma unroll
        for (int u = 0; u < 4; u++) {
            int   c  = tx + 32 * u;
            float bb = qkv_b[ch * 128 + c];
            #pragma unroll
            for (int t = 0; t < 7; t++) {
                int r = ty + 8 * t;
                if (r < NTOK) sqkv[r * 384 + ch * 128 + c] = (acc[t][u] + bb) * scl;
            }
        }
    }
    __syncthreads();

    // ---------- transpose K into sx region: kT[h*32+d][j], stride AST ----------
    {
        for (int it = 0; it < 25; it++) {
            int idx = tid + it * 256;             // over 49*128
            if (idx < NTOK * DIMC) {
                int j   = idx >> 7;
                int hdd = idx & 127;
                sx[hdd * AST + j] = sqkv[j * 384 + 128 + hdd];
            }
        }
    }
    __syncthreads();

    // ---------- S = q @ kT + (bias+mask), into sw region ----------
    {
        int h = ty >> 1, p = ty & 1;
        const float* cm = g_cmb + (size_t)((b & (NWIN - 1)) * NH + h) * (NTOK * NTOK);
        for (int i = p; i < NTOK; i += 2) {
            float a0 = 0.f, a1 = 0.f;
            const float* qrow = sqkv + i * 384 + h * HD;
            #pragma unroll
            for (int d = 0; d < HD; d++) {
                float qv = qrow[d];                       // broadcast
                a0 = fmaf(qv, sx[(h * HD + d) * AST + tx],      a0);
                a1 = fmaf(qv, sx[(h * HD + d) * AST + tx + 32], a1);
            }
            float* srow = sw + (h * NTOK + i) * AST;
            srow[tx] = a0 + cm[i * NTOK + tx];
            if (tx < NTOK - 32) srow[tx + 32] = a1 + cm[i * NTOK + tx + 32];
        }
    }
    __syncthreads();

    // ---------- softmax rows (in place) ----------
    {
        int h = ty >> 1, p = ty & 1;
        for (int i = p; i < NTOK; i += 2) {
            float* row = sw + (h * NTOK + i) * AST;
            float v0 = row[tx];
            float v1 = (tx < NTOK - 32) ? row[tx + 32] : -1e30f;
            float m  = fmaxf(v0, v1);
            #pragma unroll
            for (int o = 16; o; o >>= 1) m = fmaxf(m, __shfl_xor_sync(0xffffffffu, m, o));
            float e0 = __expf(v0 - m);
            float e1 = (tx < NTOK - 32) ? __expf(v1 - m) : 0.f;
            float s  = e0 + e1;
            #pragma unroll
            for (int o = 16; o; o >>= 1) s += __shfl_xor_sync(0xffffffffu, s, o);
            float inv = 1.f / s;
            row[tx] = e0 * inv;
            if (tx < NTOK - 32) row[tx + 32] = e1 * inv;
        }
    }
    __syncthreads();

    // ---------- O = P @ V, into sx region (kT dead) ----------
    {
        #pragma unroll
        for (int h = 0; h < NH; h++) {
            float acc[7];
            #pragma unroll
            for (int t = 0; t < 7; t++) acc[t] = 0.f;
            for (int j = 0; j < NTOK; j++) {
                float vv = sqkv[j * 384 + 256 + h * HD + tx];
                #pragma unroll
                for (int t = 0; t < 7; t++)
                    acc[t] = fmaf(sw[(h * NTOK + ty + 8 * t) * AST + j], vv, acc[t]);
            }
            #pragma unroll
            for (int t = 0; t < 7; t++) {
                int r = ty + 8 * t;
                if (r < NTOK) sx[r * DIMC + h * HD + tx] = acc[t];
            }
        }
    }
    __syncthreads();

    // ---------- stage proj W^T into sqkv region (qkv dead) ----------
    {
        const float4* wg = (const float4*)proj_w;
        #pragma unroll
        for (int it = 0; it < 16; it++) {
            int idx = tid + it * 256;
            int c   = idx >> 5;
            int kq  = idx & 31;
            float4 v = wg[c * 32 + kq];
            sqkv[(4 * kq + 0) * WTS + c] = v.x;
            sqkv[(4 * kq + 1) * WTS + c] = v.y;
            sqkv[(4 * kq + 2) * WTS + c] = v.z;
            sqkv[(4 * kq + 3) * WTS + c] = v.w;
        }
    }
    __syncthreads();

    // ---------- out = O @ projW^T + b ----------
    {
        float acc[7][4];
        #pragma unroll
        for (int t = 0; t < 7; t++)
            #pragma unroll
            for (int u = 0; u < 4; u++) acc[t][u] = 0.f;

        #pragma unroll 4
        for (int k = 0; k < DIMC; k++) {
            float wv[4];
            #pragma unroll
            for (int u = 0; u < 4; u++) wv[u] = sqkv[k * WTS + tx + 32 * u];
            #pragma unroll
            for (int t = 0; t < 7; t++) {
                float ov = sx[(ty + 8 * t) * DIMC + k];   // broadcast
                #pragma unroll
                for (int u = 0; u < 4; u++) acc[t][u] = fmaf(ov, wv[u], acc[t][u]);
            }
        }

        float* outb = out + (size_t)b * NTOK * DIMC;
        #pragma unroll
        for (int u = 0; u < 4; u++) {
            int   c  = tx + 32 * u;
            float bb = proj_b[c];
            #pragma unroll
            for (int t = 0; t < 7; t++) {
                int r = ty + 8 * t;
                if (r < NTOK) outb[r * DIMC + c] = acc[t][u] + bb;
            }
        }
    }
}

extern "C" void kernel_launch(void* const* d_in, const int* in_sizes, int n_in,
                              void* d_out, int out_size) {
    const float* x          = (const float*)d_in[0];
    const float* mask       = (const float*)d_in[1];
    const float* qkv_w      = (const float*)d_in[2];
    const float* qkv_b      = (const float*)d_in[3];
    const float* proj_w     = (const float*)d_in[4];
    const float* proj_b     = (const float*)d_in[5];
    const float* bias_table = (const float*)d_in[6];
    const int*   rel_index  = (const int*)d_in[7];
    float* out = (float*)d_out;

    size_t smem = SMEM_FLOATS * sizeof(float);
    cudaFuncSetAttribute(win_attn_kernel,
                         cudaFuncAttributeMaxDynamicSharedMemorySize, (int)smem);

    int total = NWIN * NH * NTOK * NTOK;
    prep_bias_kernel<<<(total + 255) / 256, 256>>>(mask, bias_table, rel_index);
    win_attn_kernel<<<4096, 256, smem>>>(x, qkv_w, qkv_b, proj_w, proj_b, out);
}